// round 12
// baseline (speedup 1.0000x reference)
#include <cuda_runtime.h>
#include <cstdint>

using u64 = unsigned long long;
using u32 = unsigned int;

// Problem constants
constexpr int B = 32;
constexpr int N = 131072;
constexpr int K = 1024;

// Config
constexpr int C     = 4;        // CTAs per batch (cluster)
constexpr int T     = 1024;     // threads per CTA (32 warps)
constexpr int W     = T / 32;   // warps
constexpr int S     = N / C;    // 32768 pts per CTA slice
constexpr int CH    = 128;      // points per chunk
constexpr int NCH   = S / CH;   // 256 chunks per CTA
constexpr int CPW   = NCH / W;  // 8 chunks owned per warp
constexpr int CHB   = N / CH;   // 1024 chunks per batch
constexpr int CELLS = 4096;     // 16^3 Morton cells per batch

// Static device scratch (allocation-free)
__device__ __align__(16) float4 g_tmp[B * N];  // scatter target (AoS)
__device__ __align__(16) float  g_x[B * N];    // sorted SoA
__device__ __align__(16) float  g_y[B * N];
__device__ __align__(16) float  g_z[B * N];
__device__ __align__(16) int    g_i[B * N];    // original within-batch index
__device__ int   g_hist[B * CELLS];
__device__ int   g_cur[B * CELLS];
__device__ float g_bbox[B * CHB * 6];

// ---- Morton cell id (4 bits/dim) ----
__device__ __forceinline__ u32 expand3_4(u32 v) {
    return (v & 1u) | ((v & 2u) << 2) | ((v & 4u) << 4) | ((v & 8u) << 6);
}
__device__ __forceinline__ int cell_of(float x, float y, float z) {
    int ix = min(15, max(0, (int)((x + 4.5f) * (16.0f / 9.0f))));
    int iy = min(15, max(0, (int)((y + 4.5f) * (16.0f / 9.0f))));
    int iz = min(15, max(0, (int)((z + 4.5f) * (16.0f / 9.0f))));
    return (int)(expand3_4((u32)ix) | (expand3_4((u32)iy) << 1) |
                 (expand3_4((u32)iz) << 2));
}

// ---- Preprocessing ----
__global__ void zero_hist_kernel() {
    int i = blockIdx.x * blockDim.x + threadIdx.x;
    if (i < B * CELLS) g_hist[i] = 0;
}

__global__ void cell_hist_kernel(const float* __restrict__ pts) {
    int i = blockIdx.x * blockDim.x + threadIdx.x;
    if (i >= B * N) return;
    float x = pts[3 * i], y = pts[3 * i + 1], z = pts[3 * i + 2];
    atomicAdd(&g_hist[(i / N) * CELLS + cell_of(x, y, z)], 1);
}

__global__ void cell_scan_kernel() {   // exclusive scan, one CTA per batch
    __shared__ int wt[32];
    int b = blockIdx.x, t = threadIdx.x;
    int lane = t & 31, w = t >> 5;
    int v[4], s = 0;
    #pragma unroll
    for (int j = 0; j < 4; j++) { v[j] = g_hist[b * CELLS + t * 4 + j]; s += v[j]; }
    int ps = s;
    #pragma unroll
    for (int o = 1; o < 32; o <<= 1) {
        int u = __shfl_up_sync(0xffffffffu, ps, o);
        if (lane >= o) ps += u;
    }
    if (lane == 31) wt[w] = ps;
    __syncthreads();
    if (w == 0) {
        int x = wt[lane];
        #pragma unroll
        for (int o = 1; o < 32; o <<= 1) {
            int u = __shfl_up_sync(0xffffffffu, x, o);
            if (lane >= o) x += u;
        }
        wt[lane] = x;
    }
    __syncthreads();
    int run = (w > 0 ? wt[w - 1] : 0) + (ps - s);
    #pragma unroll
    for (int j = 0; j < 4; j++) { g_cur[b * CELLS + t * 4 + j] = run; run += v[j]; }
}

__global__ void scatter_kernel(const float* __restrict__ pts) {
    int i = blockIdx.x * blockDim.x + threadIdx.x;
    if (i >= B * N) return;
    int b = i / N, j = i - b * N;
    float x = pts[3 * i], y = pts[3 * i + 1], z = pts[3 * i + 2];
    int pos = atomicAdd(&g_cur[b * CELLS + cell_of(x, y, z)], 1);
    g_tmp[b * N + pos] = make_float4(x, y, z, __int_as_float(j));  // one STG.128
}

// fused: AoS -> SoA repack + per-chunk bbox (one 128-thread block per chunk)
__global__ void bbox_repack_kernel() {
    __shared__ float rmn[3][4], rmx[3][4];
    int ch = blockIdx.x, t = threadIdx.x;
    int lane = t & 31, w = t >> 5;
    int o = ch * CH + t;
    float4 p = g_tmp[o];                 // coalesced LDG.128
    g_x[o] = p.x; g_y[o] = p.y; g_z[o] = p.z; g_i[o] = __float_as_int(p.w);
    float mnx = p.x, mxx = p.x, mny = p.y, mxy = p.y, mnz = p.z, mxz = p.z;
    #pragma unroll
    for (int s = 16; s > 0; s >>= 1) {
        mnx = fminf(mnx, __shfl_xor_sync(0xffffffffu, mnx, s));
        mxx = fmaxf(mxx, __shfl_xor_sync(0xffffffffu, mxx, s));
        mny = fminf(mny, __shfl_xor_sync(0xffffffffu, mny, s));
        mxy = fmaxf(mxy, __shfl_xor_sync(0xffffffffu, mxy, s));
        mnz = fminf(mnz, __shfl_xor_sync(0xffffffffu, mnz, s));
        mxz = fmaxf(mxz, __shfl_xor_sync(0xffffffffu, mxz, s));
    }
    if (lane == 0) {
        rmn[0][w] = mnx; rmx[0][w] = mxx;
        rmn[1][w] = mny; rmx[1][w] = mxy;
        rmn[2][w] = mnz; rmx[2][w] = mxz;
    }
    __syncthreads();
    if (t == 0) {
        float a0 = rmn[0][0], b0 = rmx[0][0];
        float a1 = rmn[1][0], b1 = rmx[1][0];
        float a2 = rmn[2][0], b2 = rmx[2][0];
        #pragma unroll
        for (int i = 1; i < 4; i++) {
            a0 = fminf(a0, rmn[0][i]); b0 = fmaxf(b0, rmx[0][i]);
            a1 = fminf(a1, rmn[1][i]); b1 = fmaxf(b1, rmx[1][i]);
            a2 = fminf(a2, rmn[2][i]); b2 = fmaxf(b2, rmx[2][i]);
        }
        float* bb = &g_bbox[ch * 6];
        bb[0] = a0; bb[1] = b0; bb[2] = a1; bb[3] = b1; bb[4] = a2; bb[5] = b2;
    }
}

// ---- cluster / mbarrier PTX helpers ----
__device__ __forceinline__ u32 smem_u32(const void* p) {
    u32 a;
    asm("{ .reg .u64 t; cvta.to.shared.u64 t, %1; cvt.u32.u64 %0, t; }"
        : "=r"(a) : "l"(p));
    return a;
}
__device__ __forceinline__ u32 mapa_rank(u32 addr, u32 r) {
    u32 o;
    asm("mapa.shared::cluster.u32 %0, %1, %2;" : "=r"(o) : "r"(addr), "r"(r));
    return o;
}
__device__ __forceinline__ void st_cluster_u64(u32 addr, u64 v) {
    asm volatile("st.shared::cluster.b64 [%0], %1;" :: "r"(addr), "l"(v) : "memory");
}
__device__ __forceinline__ void mbar_init(u32 addr, u32 count) {
    asm volatile("mbarrier.init.shared.b64 [%0], %1;" :: "r"(addr), "r"(count) : "memory");
}
__device__ __forceinline__ void mbar_arrive_cluster(u32 addr) {
    asm volatile("mbarrier.arrive.release.cluster.shared::cluster.b64 _, [%0];"
                 :: "r"(addr) : "memory");
}
__device__ __forceinline__ void mbar_wait_cluster(u32 addr, u32 parity) {
    asm volatile(
        "{\n\t.reg .pred P;\n\t"
        "WL_%=:\n\t"
        "mbarrier.try_wait.parity.acquire.cluster.shared::cta.b64 P, [%0], %1, 0x989680;\n\t"
        "@P bra.uni WD_%=;\n\t"
        "bra.uni WL_%=;\n\t"
        "WD_%=:\n\t}"
        :: "r"(addr), "r"(parity) : "memory");
}
__device__ __forceinline__ void cluster_sync_asm() {
    asm volatile("barrier.cluster.arrive.aligned;" ::: "memory");
    asm volatile("barrier.cluster.wait.aligned;" ::: "memory");
}

// ---- SMEM layout (bytes) ----
constexpr int SM_DIST = 0;                         // S floats  = 131072
constexpr int SM_BOX  = SM_DIST + S * 4;           // NCH*6 f   =   6144
constexpr int SM_CB   = SM_BOX + NCH * 24;         // NCH u64   =   2048
constexpr int SM_CX   = SM_CB + NCH * 8;           // NCH f
constexpr int SM_CY   = SM_CX + NCH * 4;
constexpr int SM_CZ   = SM_CY + NCH * 4;
constexpr int SM_MBAR = SM_CZ + NCH * 4;           // 2 u64
constexpr int SM_SLOT = SM_MBAR + 16;              // 2*C*32 bytes
constexpr int SMEM_TOTAL = SM_SLOT + 2 * C * 32;   // ~142.8 KB

struct __align__(32) Slot {
    u32 lo, hi;        // packed best: (dist_bits<<32) | ~origidx
    float x, y, z;
    float pad0, pad1, pad2;
};

__global__ void __cluster_dims__(C, 1, 1) __launch_bounds__(T, 1)
fps_kernel(const float* __restrict__ pts, const int* __restrict__ init_idx,
           float* __restrict__ out)
{
    extern __shared__ char smem[];
    float4* sd4  = (float4*)(smem + SM_DIST);
    float*  sbox = (float*)(smem + SM_BOX);
    u64*    scb  = (u64*)(smem + SM_CB);
    float*  scx  = (float*)(smem + SM_CX);
    float*  scy  = (float*)(smem + SM_CY);
    float*  scz  = (float*)(smem + SM_CZ);
    Slot*   sl   = (Slot*)(smem + SM_SLOT);

    const u32 mbar_base = smem_u32(smem + SM_MBAR);
    const u32 slot_base = smem_u32(smem + SM_SLOT);

    const int rank = blockIdx.x;
    const int b    = blockIdx.y;
    const int t    = threadIdx.x;
    const int warp = t >> 5, lane = t & 31;
    const int gbase = b * N + rank * S;
    const int bbase = (b * CHB + rank * NCH) * 6;

    const float4* __restrict__ gx4 = (const float4*)(g_x + gbase);
    const float4* __restrict__ gy4 = (const float4*)(g_y + gbase);
    const float4* __restrict__ gz4 = (const float4*)(g_z + gbase);
    const int4*   __restrict__ gi4 = (const int4*)(g_i + gbase);

    // ---- init ----
    #pragma unroll
    for (int j = 0; j < S / (4 * T); j++)
        sd4[t + j * T] = make_float4(1e10f, 1e10f, 1e10f, 1e10f);
    for (int i = t; i < NCH * 6; i += T) sbox[i] = g_bbox[bbase + i];
    if (t < NCH) {
        scb[t] = ((u64)__float_as_uint(1e10f)) << 32;   // forces touch at k=1
        scx[t] = 0.f; scy[t] = 0.f; scz[t] = 0.f;
    }
    if (t == 0) {
        mbar_init(mbar_base + 0, C);
        mbar_init(mbar_base + 8, C);
    }

    const int idx0 = init_idx[b];
    float lx = pts[3 * (b * N + idx0) + 0];
    float ly = pts[3 * (b * N + idx0) + 1];
    float lz = pts[3 * (b * N + idx0) + 2];
    if (rank == 0 && t == 0) {
        out[(b * K + 0) * 3 + 0] = lx;
        out[(b * K + 0) * 3 + 1] = ly;
        out[(b * K + 0) * 3 + 2] = lz;
    }
    __syncthreads();
    cluster_sync_asm();   // mbarrier inits visible before any remote arrive

    int par0 = 0, par1 = 0;

    // ---- K-1 sequential iterations ----
    for (int k = 1; k < K; k++) {
        const int ph = k & 1;

        // fused A+B: lanes 0..7 bound-check this warp's 8 owned chunks
        bool touched = false;
        if (lane < CPW) {
            int c = warp + (lane << 5);
            const float* bb = &sbox[c * 6];
            float dx = fmaxf(0.0f, fmaxf(bb[0] - lx, lx - bb[1]));
            float dy = fmaxf(0.0f, fmaxf(bb[2] - ly, ly - bb[3]));
            float dz = fmaxf(0.0f, fmaxf(bb[4] - lz, lz - bb[5]));
            float lb2 = __fmaf_rn(dx, dx, __fmaf_rn(dy, dy, dz * dz));
            float cub = __uint_as_float((u32)(scb[c] >> 32));
            touched = (lb2 * 0.99999f < cub);       // conservative margin
        }
        unsigned mask = __ballot_sync(0xffffffffu, touched);

        while (mask) {
            int l = __ffs(mask) - 1;
            mask &= mask - 1;
            int c = warp + (l << 5);                // owned chunk id
            int f = c * 32 + lane;                  // float4 index, coalesced
            float4 X = gx4[f];
            float4 Y = gy4[f];
            float4 Z = gz4[f];
            int4   I = gi4[f];
            float4 D = sd4[f];
            const float* Xv = (const float*)&X;
            const float* Yv = (const float*)&Y;
            const float* Zv = (const float*)&Z;
            const int*   Iv = (const int*)&I;
            float* Dv = (float*)&D;
            u64 bk = 0ULL;
            float bx = 0.f, by = 0.f, bz = 0.f;
            #pragma unroll
            for (int cc = 0; cc < 4; cc++) {
                float dx = Xv[cc] - lx, dy = Yv[cc] - ly, dz = Zv[cc] - lz;
                float d2 = __fmaf_rn(dx, dx, __fmaf_rn(dy, dy, dz * dz));
                float nd = fminf(Dv[cc], d2);
                Dv[cc] = nd;
                u64 key = (((u64)__float_as_uint(nd)) << 32) |
                          (u32)(~(u32)Iv[cc]);
                if (key > bk) { bk = key; bx = Xv[cc]; by = Yv[cc]; bz = Zv[cc]; }
            }
            sd4[f] = D;
            #pragma unroll
            for (int o = 16; o > 0; o >>= 1) {
                u64   ok = __shfl_xor_sync(0xffffffffu, bk, o);
                float ox = __shfl_xor_sync(0xffffffffu, bx, o);
                float oy = __shfl_xor_sync(0xffffffffu, by, o);
                float oz = __shfl_xor_sync(0xffffffffu, bz, o);
                if (ok > bk) { bk = ok; bx = ox; by = oy; bz = oz; }
            }
            if (lane == 0) {
                scb[c] = bk;
                scx[c] = bx; scy[c] = by; scz[c] = bz;
            }
        }
        __syncthreads();   // scb/scx/scy/scz ready for warp0's scan

        // phase C: warp0 scans 256 chunk keys, pushes best (key+coords)
        if (warp == 0) {
            u64 bk = 0ULL; int bc = 0;
            #pragma unroll
            for (int i = 0; i < NCH / 32; i++) {
                u64 e = scb[lane + 32 * i];
                if (e > bk) { bk = e; bc = lane + 32 * i; }
            }
            #pragma unroll
            for (int o = 16; o > 0; o >>= 1) {
                u64 ok = __shfl_xor_sync(0xffffffffu, bk, o);
                int oc = __shfl_xor_sync(0xffffffffu, bc, o);
                if (ok > bk) { bk = ok; bc = oc; }
            }
            if (lane == 0) {
                u64 xy = ((u64)__float_as_uint(scy[bc]) << 32) |
                         (u64)__float_as_uint(scx[bc]);
                u64 z0 = (u64)__float_as_uint(scz[bc]);
                u32 my_slot = slot_base + (u32)(ph * C + rank) * 32u;
                u32 my_mbar = mbar_base + (u32)ph * 8u;
                #pragma unroll
                for (int r = 0; r < C; r++) {
                    u32 sa = mapa_rank(my_slot, (u32)r);
                    u32 ma = mapa_rank(my_mbar, (u32)r);
                    st_cluster_u64(sa +  0, bk);
                    st_cluster_u64(sa +  8, xy);
                    st_cluster_u64(sa + 16, z0);
                    mbar_arrive_cluster(ma);   // release: orders the 3 stores
                }
            }
        }

        // every warp independently waits for all 4 ranks, then picks winner
        int par = ph ? par1 : par0;
        if (lane == 0)
            mbar_wait_cluster(mbar_base + (u32)ph * 8u, (u32)par);
        __syncwarp();
        if (ph) par1 ^= 1; else par0 ^= 1;

        u64 gb = 0ULL;
        float nx = 0.f, ny = 0.f, nz = 0.f;
        #pragma unroll
        for (int r = 0; r < C; r++) {
            const char* sp = smem + SM_SLOT + (ph * C + r) * 32;
            u64 key = *(const u64*)(sp + 0);
            u64 xy  = *(const u64*)(sp + 8);
            u64 z0  = *(const u64*)(sp + 16);
            if (key > gb) {
                gb = key;
                nx = __uint_as_float((u32)(xy & 0xffffffffull));
                ny = __uint_as_float((u32)(xy >> 32));
                nz = __uint_as_float((u32)(z0 & 0xffffffffull));
            }
        }
        lx = nx; ly = ny; lz = nz;

        if (rank == 0 && t == 0) {
            out[(b * K + k) * 3 + 0] = lx;
            out[(b * K + k) * 3 + 1] = ly;
            out[(b * K + k) * 3 + 2] = lz;
        }
    }

    cluster_sync_asm();   // keep SMEM alive until all peer traffic retired
}

extern "C" void kernel_launch(void* const* d_in, const int* in_sizes, int n_in,
                              void* d_out, int out_size) {
    const float* pts  = (const float*)d_in[0];
    const int*   init = (const int*)d_in[1];
    float*       out  = (float*)d_out;

    cudaFuncSetAttribute(fps_kernel,
                         cudaFuncAttributeMaxDynamicSharedMemorySize, SMEM_TOTAL);

    const int tot = B * N;
    zero_hist_kernel<<<(B * CELLS + 255) / 256, 256>>>();
    cell_hist_kernel<<<(tot + 255) / 256, 256>>>(pts);
    cell_scan_kernel<<<B, 1024>>>();
    scatter_kernel<<<(tot + 255) / 256, 256>>>(pts);
    bbox_repack_kernel<<<B * CHB, CH>>>();

    dim3 grid(C, B, 1);
    fps_kernel<<<grid, T, SMEM_TOTAL>>>(pts, init, out);
}

// round 13
// speedup vs baseline: 1.2182x; 1.2182x over previous
#include <cuda_runtime.h>
#include <cooperative_groups.h>
#include <cstdint>

namespace cg = cooperative_groups;
using u64 = unsigned long long;
using u32 = unsigned int;

// Problem constants
constexpr int B = 32;
constexpr int N = 131072;
constexpr int K = 1024;

// Config
constexpr int C     = 4;        // CTAs per batch (cluster)
constexpr int T     = 1024;     // threads per CTA (32 warps)
constexpr int W     = T / 32;   // warps per CTA
constexpr int S     = N / C;    // 32768 pts per CTA slice
constexpr int CH    = 128;      // points per chunk
constexpr int NCH   = S / CH;   // 256 chunks per CTA
constexpr int CPW   = NCH / W;  // 8 chunks owned per warp
constexpr int CHB   = N / CH;   // 1024 chunks per batch
constexpr int CELLS = 4096;     // 16^3 Morton cells per batch

// Static device scratch (allocation-free)
__device__ __align__(16) float4 g_tmp[B * N];  // scatter target (AoS)
__device__ __align__(16) float  g_x[B * N];    // sorted SoA
__device__ __align__(16) float  g_y[B * N];
__device__ __align__(16) float  g_z[B * N];
__device__ __align__(16) int    g_i[B * N];    // original within-batch index
__device__ int   g_hist[B * CELLS];
__device__ int   g_cur[B * CELLS];
__device__ float g_bbox[B * CHB * 6];

// ---- Morton cell id (4 bits/dim) ----
__device__ __forceinline__ u32 expand3_4(u32 v) {
    return (v & 1u) | ((v & 2u) << 2) | ((v & 4u) << 4) | ((v & 8u) << 6);
}
__device__ __forceinline__ int cell_of(float x, float y, float z) {
    int ix = min(15, max(0, (int)((x + 4.5f) * (16.0f / 9.0f))));
    int iy = min(15, max(0, (int)((y + 4.5f) * (16.0f / 9.0f))));
    int iz = min(15, max(0, (int)((z + 4.5f) * (16.0f / 9.0f))));
    return (int)(expand3_4((u32)ix) | (expand3_4((u32)iy) << 1) |
                 (expand3_4((u32)iz) << 2));
}

// ---- Preprocessing ----
__global__ void zero_hist_kernel() {
    int i = blockIdx.x * blockDim.x + threadIdx.x;
    if (i < B * CELLS) g_hist[i] = 0;
}

__global__ void cell_hist_kernel(const float* __restrict__ pts) {
    int i = blockIdx.x * blockDim.x + threadIdx.x;
    if (i >= B * N) return;
    float x = pts[3 * i], y = pts[3 * i + 1], z = pts[3 * i + 2];
    atomicAdd(&g_hist[(i / N) * CELLS + cell_of(x, y, z)], 1);
}

__global__ void cell_scan_kernel() {   // exclusive scan, one CTA per batch
    __shared__ int wt[32];
    int b = blockIdx.x, t = threadIdx.x;
    int lane = t & 31, w = t >> 5;
    int v[4], s = 0;
    #pragma unroll
    for (int j = 0; j < 4; j++) { v[j] = g_hist[b * CELLS + t * 4 + j]; s += v[j]; }
    int ps = s;
    #pragma unroll
    for (int o = 1; o < 32; o <<= 1) {
        int u = __shfl_up_sync(0xffffffffu, ps, o);
        if (lane >= o) ps += u;
    }
    if (lane == 31) wt[w] = ps;
    __syncthreads();
    if (w == 0) {
        int x = wt[lane];
        #pragma unroll
        for (int o = 1; o < 32; o <<= 1) {
            int u = __shfl_up_sync(0xffffffffu, x, o);
            if (lane >= o) x += u;
        }
        wt[lane] = x;
    }
    __syncthreads();
    int run = (w > 0 ? wt[w - 1] : 0) + (ps - s);
    #pragma unroll
    for (int j = 0; j < 4; j++) { g_cur[b * CELLS + t * 4 + j] = run; run += v[j]; }
}

__global__ void scatter_kernel(const float* __restrict__ pts) {
    int i = blockIdx.x * blockDim.x + threadIdx.x;
    if (i >= B * N) return;
    int b = i / N, j = i - b * N;
    float x = pts[3 * i], y = pts[3 * i + 1], z = pts[3 * i + 2];
    int pos = atomicAdd(&g_cur[b * CELLS + cell_of(x, y, z)], 1);
    g_tmp[b * N + pos] = make_float4(x, y, z, __int_as_float(j));  // one STG.128
}

// fused: AoS -> SoA repack + per-chunk bbox (one 128-thread block per chunk)
__global__ void bbox_repack_kernel() {
    __shared__ float rmn[3][4], rmx[3][4];
    int ch = blockIdx.x, t = threadIdx.x;
    int lane = t & 31, w = t >> 5;
    int o = ch * CH + t;
    float4 p = g_tmp[o];                 // coalesced LDG.128
    g_x[o] = p.x; g_y[o] = p.y; g_z[o] = p.z; g_i[o] = __float_as_int(p.w);
    float mnx = p.x, mxx = p.x, mny = p.y, mxy = p.y, mnz = p.z, mxz = p.z;
    #pragma unroll
    for (int s = 16; s > 0; s >>= 1) {
        mnx = fminf(mnx, __shfl_xor_sync(0xffffffffu, mnx, s));
        mxx = fmaxf(mxx, __shfl_xor_sync(0xffffffffu, mxx, s));
        mny = fminf(mny, __shfl_xor_sync(0xffffffffu, mny, s));
        mxy = fmaxf(mxy, __shfl_xor_sync(0xffffffffu, mxy, s));
        mnz = fminf(mnz, __shfl_xor_sync(0xffffffffu, mnz, s));
        mxz = fmaxf(mxz, __shfl_xor_sync(0xffffffffu, mxz, s));
    }
    if (lane == 0) {
        rmn[0][w] = mnx; rmx[0][w] = mxx;
        rmn[1][w] = mny; rmx[1][w] = mxy;
        rmn[2][w] = mnz; rmx[2][w] = mxz;
    }
    __syncthreads();
    if (t == 0) {
        float a0 = rmn[0][0], b0 = rmx[0][0];
        float a1 = rmn[1][0], b1 = rmx[1][0];
        float a2 = rmn[2][0], b2 = rmx[2][0];
        #pragma unroll
        for (int i = 1; i < 4; i++) {
            a0 = fminf(a0, rmn[0][i]); b0 = fmaxf(b0, rmx[0][i]);
            a1 = fminf(a1, rmn[1][i]); b1 = fmaxf(b1, rmx[1][i]);
            a2 = fminf(a2, rmn[2][i]); b2 = fmaxf(b2, rmx[2][i]);
        }
        float* bb = &g_bbox[ch * 6];
        bb[0] = a0; bb[1] = b0; bb[2] = a1; bb[3] = b1; bb[4] = a2; bb[5] = b2;
    }
}

// ---- Main FPS kernel ----
struct __align__(32) Slot {
    u32 lo, hi;        // packed best: (dist_bits<<32) | ~origidx
    float x, y, z;
    float pad0, pad1, pad2;
};

// SMEM layout (bytes)
constexpr int SM_DIST = 0;                         // S floats  = 131072
constexpr int SM_BOX  = SM_DIST + S * 4;           // NCH*6 f   =   6144
constexpr int SM_CB   = SM_BOX + NCH * 24;         // NCH u64   =   2048
constexpr int SM_CX   = SM_CB + NCH * 8;           // NCH f
constexpr int SM_CY   = SM_CX + NCH * 4;
constexpr int SM_CZ   = SM_CY + NCH * 4;
constexpr int SM_SL   = SM_CZ + NCH * 4;           // Slot[2][C] = 256
constexpr int SMEM_TOTAL = SM_SL + 2 * C * 32;     // ~142.8 KB

__global__ void __cluster_dims__(C, 1, 1) __launch_bounds__(T, 1)
fps_kernel(const float* __restrict__ pts, const int* __restrict__ init_idx,
           float* __restrict__ out)
{
    extern __shared__ char smem[];
    float4* sd4  = (float4*)(smem + SM_DIST);
    float*  sbox = (float*)(smem + SM_BOX);
    u64*    scb  = (u64*)(smem + SM_CB);
    float*  scx  = (float*)(smem + SM_CX);
    float*  scy  = (float*)(smem + SM_CY);
    float*  scz  = (float*)(smem + SM_CZ);
    Slot*   sl   = (Slot*)(smem + SM_SL);

    cg::cluster_group cluster = cg::this_cluster();
    const int rank = blockIdx.x;
    const int b    = blockIdx.y;
    const int t    = threadIdx.x;
    const int warp = t >> 5, lane = t & 31;
    const int gbase = b * N + rank * S;
    const int bbase = (b * CHB + rank * NCH) * 6;

    const float4* __restrict__ gx4 = (const float4*)(g_x + gbase);
    const float4* __restrict__ gy4 = (const float4*)(g_y + gbase);
    const float4* __restrict__ gz4 = (const float4*)(g_z + gbase);
    const int4*   __restrict__ gi4 = (const int4*)(g_i + gbase);

    // ---- init ----
    #pragma unroll
    for (int j = 0; j < S / (4 * T); j++)
        sd4[t + j * T] = make_float4(1e10f, 1e10f, 1e10f, 1e10f);
    for (int i = t; i < NCH * 6; i += T) sbox[i] = g_bbox[bbase + i];
    if (t < NCH) {
        scb[t] = ((u64)__float_as_uint(1e10f)) << 32;   // forces touch at k=1
        scx[t] = 0.f; scy[t] = 0.f; scz[t] = 0.f;
    }

    const int idx0 = init_idx[b];
    float lx = pts[3 * (b * N + idx0) + 0];
    float ly = pts[3 * (b * N + idx0) + 1];
    float lz = pts[3 * (b * N + idx0) + 2];
    if (rank == 0 && t == 0) {
        out[(b * K + 0) * 3 + 0] = lx;
        out[(b * K + 0) * 3 + 1] = ly;
        out[(b * K + 0) * 3 + 2] = lz;
    }
    __syncthreads();

    // ---- K-1 sequential iterations ----
    for (int k = 1; k < K; k++) {
        const int ph = k & 1;

        // fused A+B: lanes 0..7 bound-check this warp's 8 owned chunks
        // (chunk state is warp-private: no barrier/atomics between check+update)
        bool touched = false;
        if (lane < CPW) {
            int c = warp + (lane << 5);
            const float* bb = &sbox[c * 6];
            float dx = fmaxf(0.0f, fmaxf(bb[0] - lx, lx - bb[1]));
            float dy = fmaxf(0.0f, fmaxf(bb[2] - ly, ly - bb[3]));
            float dz = fmaxf(0.0f, fmaxf(bb[4] - lz, lz - bb[5]));
            float lb2 = __fmaf_rn(dx, dx, __fmaf_rn(dy, dy, dz * dz));
            float cub = __uint_as_float((u32)(scb[c] >> 32));
            touched = (lb2 * 0.99999f < cub);       // conservative margin
        }
        unsigned mask = __ballot_sync(0xffffffffu, touched);

        while (mask) {
            int l = __ffs(mask) - 1;
            mask &= mask - 1;
            int c = warp + (l << 5);                // owned chunk id
            int f = c * 32 + lane;                  // float4 index, coalesced
            float4 X = gx4[f];
            float4 Y = gy4[f];
            float4 Z = gz4[f];
            int4   I = gi4[f];
            float4 D = sd4[f];
            const float* Xv = (const float*)&X;
            const float* Yv = (const float*)&Y;
            const float* Zv = (const float*)&Z;
            const int*   Iv = (const int*)&I;
            float* Dv = (float*)&D;
            u64 bk = 0ULL;
            float bx = 0.f, by = 0.f, bz = 0.f;
            #pragma unroll
            for (int cc = 0; cc < 4; cc++) {
                float dx = Xv[cc] - lx, dy = Yv[cc] - ly, dz = Zv[cc] - lz;
                float d2 = __fmaf_rn(dx, dx, __fmaf_rn(dy, dy, dz * dz));
                float nd = fminf(Dv[cc], d2);
                Dv[cc] = nd;
                u64 key = (((u64)__float_as_uint(nd)) << 32) |
                          (u32)(~(u32)Iv[cc]);
                if (key > bk) { bk = key; bx = Xv[cc]; by = Yv[cc]; bz = Zv[cc]; }
            }
            sd4[f] = D;
            #pragma unroll
            for (int o = 16; o > 0; o >>= 1) {
                u64   ok = __shfl_xor_sync(0xffffffffu, bk, o);
                float ox = __shfl_xor_sync(0xffffffffu, bx, o);
                float oy = __shfl_xor_sync(0xffffffffu, by, o);
                float oz = __shfl_xor_sync(0xffffffffu, bz, o);
                if (ok > bk) { bk = ok; bx = ox; by = oy; bz = oz; }
            }
            if (lane == 0) {
                scb[c] = bk;
                scx[c] = bx; scy[c] = by; scz[c] = bz;
            }
        }
        __syncthreads();   // scb/scx/scy/scz ready for warp0's scan

        // phase C: warp0 reduces 256 chunk keys, pushes best (key+coords)
        if (warp == 0) {
            u64 bk = 0ULL; int bc = 0;
            #pragma unroll
            for (int i = 0; i < NCH / 32; i++) {
                u64 e = scb[lane + 32 * i];
                if (e > bk) { bk = e; bc = lane + 32 * i; }
            }
            #pragma unroll
            for (int o = 16; o > 0; o >>= 1) {
                u64 ok = __shfl_xor_sync(0xffffffffu, bk, o);
                int oc = __shfl_xor_sync(0xffffffffu, bc, o);
                if (ok > bk) { bk = ok; bc = oc; }
            }
            if (lane == 0) {
                Slot* my = &sl[ph * C + rank];
                uint4 w = make_uint4((u32)(bk & 0xffffffffull),
                                     (u32)(bk >> 32),
                                     __float_as_uint(scx[bc]),
                                     __float_as_uint(scy[bc]));
                float cz = scz[bc];
                #pragma unroll
                for (int r = 0; r < C; r++) {
                    Slot* p = (Slot*)cluster.map_shared_rank(my, r);
                    *(uint4*)p = w;
                    p->z = cz;
                }
            }
        }

        cluster.sync();   // HW-sleep barrier; orders remote slot stores

        // every thread picks the cluster winner from local slots (coords incl.)
        u64 gb = 0ULL;
        float nx = 0.f, ny = 0.f, nz = 0.f;
        #pragma unroll
        for (int r = 0; r < C; r++) {
            const Slot* p = &sl[ph * C + r];
            uint4 w = *(const uint4*)p;
            float z = p->z;
            u64 v = ((u64)w.y << 32) | w.x;
            if (v > gb) {
                gb = v;
                nx = __uint_as_float(w.z);
                ny = __uint_as_float(w.w);
                nz = z;
            }
        }
        lx = nx; ly = ny; lz = nz;

        if (rank == 0 && t == 0) {
            out[(b * K + k) * 3 + 0] = lx;
            out[(b * K + k) * 3 + 1] = ly;
            out[(b * K + k) * 3 + 2] = lz;
        }
    }

    cluster.sync();   // keep SMEM alive until all peer traffic retired
}

extern "C" void kernel_launch(void* const* d_in, const int* in_sizes, int n_in,
                              void* d_out, int out_size) {
    const float* pts  = (const float*)d_in[0];
    const int*   init = (const int*)d_in[1];
    float*       out  = (float*)d_out;

    cudaFuncSetAttribute(fps_kernel,
                         cudaFuncAttributeMaxDynamicSharedMemorySize, SMEM_TOTAL);

    const int tot = B * N;
    zero_hist_kernel<<<(B * CELLS + 255) / 256, 256>>>();
    cell_hist_kernel<<<(tot + 255) / 256, 256>>>(pts);
    cell_scan_kernel<<<B, 1024>>>();
    scatter_kernel<<<(tot + 255) / 256, 256>>>(pts);
    bbox_repack_kernel<<<B * CHB, CH>>>();

    dim3 grid(C, B, 1);
    fps_kernel<<<grid, T, SMEM_TOTAL>>>(pts, init, out);
}

// round 14
// speedup vs baseline: 1.5303x; 1.2562x over previous
#include <cuda_runtime.h>
#include <cooperative_groups.h>
#include <cstdint>

namespace cg = cooperative_groups;
using u64 = unsigned long long;
using u32 = unsigned int;

// Problem constants
constexpr int B = 32;
constexpr int N = 131072;
constexpr int K = 1024;

// Config
constexpr int C     = 4;        // CTAs per batch (cluster)
constexpr int T     = 1024;     // threads per CTA (32 warps)
constexpr int W     = T / 32;   // warps per CTA
constexpr int S     = N / C;    // 32768 pts per CTA slice
constexpr int CH    = 128;      // points per chunk
constexpr int NCH   = S / CH;   // 256 chunks per CTA
constexpr int CELLS = 4096;     // 16^3 Morton cells per batch

// Static device scratch (allocation-free): sorted SoA
__device__ __align__(16) float g_x[B * N];
__device__ __align__(16) float g_y[B * N];
__device__ __align__(16) float g_z[B * N];
__device__ __align__(16) int   g_i[B * N];   // original within-batch index

// ---- Morton cell id (4 bits/dim) ----
__device__ __forceinline__ u32 expand3_4(u32 v) {
    return (v & 1u) | ((v & 2u) << 2) | ((v & 4u) << 4) | ((v & 8u) << 6);
}
__device__ __forceinline__ int cell_of(float x, float y, float z) {
    int ix = min(15, max(0, (int)((x + 4.5f) * (16.0f / 9.0f))));
    int iy = min(15, max(0, (int)((y + 4.5f) * (16.0f / 9.0f))));
    int iz = min(15, max(0, (int)((z + 4.5f) * (16.0f / 9.0f))));
    return (int)(expand3_4((u32)ix) | (expand3_4((u32)iy) << 1) |
                 (expand3_4((u32)iz) << 2));
}

// ---- Main FPS kernel (self-contained: sort + bbox + FPS) ----
struct __align__(32) Slot {
    u32 lo, hi;        // packed best: (dist_bits<<32) | ~origidx
    float x, y, z;
    float pad0, pad1, pad2;
};

// SMEM layout (bytes) — dist region doubles as sort scratch in the prologue
constexpr int SM_DIST = 0;                         // S floats  = 131072
constexpr int SM_BOX  = SM_DIST + S * 4;           // NCH*6 f   =   6144
constexpr int SM_CB   = SM_BOX + NCH * 24;         // NCH u64   =   2048
constexpr int SM_CX   = SM_CB + NCH * 8;           // NCH f
constexpr int SM_CY   = SM_CX + NCH * 4;
constexpr int SM_CZ   = SM_CY + NCH * 4;
constexpr int SM_WL   = SM_CZ + NCH * 4;           // NCH u32 worklist
constexpr int SM_WC   = SM_WL + NCH * 4;           // 2 u32 + pad
constexpr int SM_SL   = SM_WC + 16;                // Slot[2][C]
constexpr int SMEM_TOTAL = SM_SL + 2 * C * 32;     // ~143.8 KB

__global__ void __cluster_dims__(C, 1, 1) __launch_bounds__(T, 1)
fps_kernel(const float* __restrict__ pts, const int* __restrict__ init_idx,
           float* __restrict__ out)
{
    extern __shared__ char smem[];
    float4* sd4  = (float4*)(smem + SM_DIST);
    float*  sbox = (float*)(smem + SM_BOX);
    u64*    scb  = (u64*)(smem + SM_CB);
    float*  scx  = (float*)(smem + SM_CX);
    float*  scy  = (float*)(smem + SM_CY);
    float*  scz  = (float*)(smem + SM_CZ);
    u32*    swl  = (u32*)(smem + SM_WL);
    u32*    swc  = (u32*)(smem + SM_WC);
    Slot*   sl   = (Slot*)(smem + SM_SL);

    // sort scratch overlays the dist region (freed before dist init)
    u32* PH = (u32*)(smem + SM_DIST);        // local hist   [CELLS]
    u32* PC = PH + CELLS;                    // cur/base     [CELLS]
    int* PW = (int*)(PC + CELLS);            // warp totals  [32]

    cg::cluster_group cluster = cg::this_cluster();
    const int rank = blockIdx.x;
    const int b    = blockIdx.y;
    const int t    = threadIdx.x;
    const int warp = t >> 5, lane = t & 31;
    const int bOff  = b * N;
    const int gbase = bOff + rank * S;       // slice start (input AND sorted)

    // ======================= in-kernel preprocessing =======================
    // (1) local histogram in SMEM
    #pragma unroll
    for (int j = 0; j < CELLS / T; j++) PH[t + j * T] = 0;
    __syncthreads();
    for (int i = t; i < S; i += T) {
        int gi = gbase + i;
        float x = pts[3 * gi], y = pts[3 * gi + 1], z = pts[3 * gi + 2];
        atomicAdd(&PH[cell_of(x, y, z)], 1u);
    }
    __syncthreads();
    cluster.sync();   // peers' hists complete

    // (2) combine peer hists (DSMEM) + exclusive scan -> per-CTA base counters
    {
        int v[4], mb[4];
        #pragma unroll
        for (int j = 0; j < 4; j++) {
            int cell = t * 4 + j;
            int tot = 0, base = 0;
            #pragma unroll
            for (int r = 0; r < C; r++) {
                u32* hp = (u32*)cluster.map_shared_rank(PH + cell, r);
                int h = (int)*hp;
                if (r < rank) base += h;
                tot += h;
            }
            v[j] = tot; mb[j] = base;
        }
        int s = v[0] + v[1] + v[2] + v[3];
        int ps = s;
        #pragma unroll
        for (int o = 1; o < 32; o <<= 1) {
            int u = __shfl_up_sync(0xffffffffu, ps, o);
            if (lane >= o) ps += u;
        }
        if (lane == 31) PW[warp] = ps;
        __syncthreads();
        if (warp == 0) {
            int x = PW[lane];
            #pragma unroll
            for (int o = 1; o < 32; o <<= 1) {
                int u = __shfl_up_sync(0xffffffffu, x, o);
                if (lane >= o) x += u;
            }
            PW[lane] = x;
        }
        __syncthreads();
        int run = (warp > 0 ? PW[warp - 1] : 0) + (ps - s);
        #pragma unroll
        for (int j = 0; j < 4; j++) {
            PC[t * 4 + j] = (u32)(run + mb[j]);
            run += v[j];
        }
    }
    __syncthreads();

    // (3) scatter own input slice into batch-sorted SoA arrays
    for (int i = t; i < S; i += T) {
        int gi = gbase + i;
        float x = pts[3 * gi], y = pts[3 * gi + 1], z = pts[3 * gi + 2];
        int cell = cell_of(x, y, z);
        int pos = (int)atomicAdd(&PC[cell], 1u);
        int o = bOff + pos;
        g_x[o] = x; g_y[o] = y; g_z[o] = z; g_i[o] = gi - bOff;
    }
    __threadfence();
    __syncthreads();
    cluster.sync();   // all batch points sorted & visible

    // sorted-slice views
    const float4* __restrict__ gx4 = (const float4*)(g_x + gbase);
    const float4* __restrict__ gy4 = (const float4*)(g_y + gbase);
    const float4* __restrict__ gz4 = (const float4*)(g_z + gbase);
    const int4*   __restrict__ gi4 = (const int4*)(g_i + gbase);

    // (4) per-chunk bboxes straight into SMEM (one warp per chunk)
    for (int c = warp; c < NCH; c += W) {
        int f = c * 32 + lane;
        float4 X = gx4[f], Y = gy4[f], Z = gz4[f];
        float mnx = fminf(fminf(X.x, X.y), fminf(X.z, X.w));
        float mxx = fmaxf(fmaxf(X.x, X.y), fmaxf(X.z, X.w));
        float mny = fminf(fminf(Y.x, Y.y), fminf(Y.z, Y.w));
        float mxy = fmaxf(fmaxf(Y.x, Y.y), fmaxf(Y.z, Y.w));
        float mnz = fminf(fminf(Z.x, Z.y), fminf(Z.z, Z.w));
        float mxz = fmaxf(fmaxf(Z.x, Z.y), fmaxf(Z.z, Z.w));
        #pragma unroll
        for (int s2 = 16; s2 > 0; s2 >>= 1) {
            mnx = fminf(mnx, __shfl_xor_sync(0xffffffffu, mnx, s2));
            mxx = fmaxf(mxx, __shfl_xor_sync(0xffffffffu, mxx, s2));
            mny = fminf(mny, __shfl_xor_sync(0xffffffffu, mny, s2));
            mxy = fmaxf(mxy, __shfl_xor_sync(0xffffffffu, mxy, s2));
            mnz = fminf(mnz, __shfl_xor_sync(0xffffffffu, mnz, s2));
            mxz = fmaxf(mxz, __shfl_xor_sync(0xffffffffu, mxz, s2));
        }
        if (lane == 0) {
            float* bb = &sbox[c * 6];
            bb[0] = mnx; bb[1] = mxx; bb[2] = mny;
            bb[3] = mxy; bb[4] = mnz; bb[5] = mxz;
        }
    }
    __syncthreads();   // sbox done before dist init reuses nothing of it

    // (5) dist init (overwrites sort scratch) + chunk state + first point
    #pragma unroll
    for (int j = 0; j < S / (4 * T); j++)
        sd4[t + j * T] = make_float4(1e10f, 1e10f, 1e10f, 1e10f);
    if (t < NCH) {
        scb[t] = ((u64)__float_as_uint(1e10f)) << 32;   // forces touch at k=1
        scx[t] = 0.f; scy[t] = 0.f; scz[t] = 0.f;
    }
    if (t == 0) { swc[0] = 0; swc[1] = 0; }

    const int idx0 = init_idx[b];
    float lx = pts[3 * (bOff + idx0) + 0];
    float ly = pts[3 * (bOff + idx0) + 1];
    float lz = pts[3 * (bOff + idx0) + 2];
    if (rank == 0 && t == 0) {
        out[(b * K + 0) * 3 + 0] = lx;
        out[(b * K + 0) * 3 + 1] = ly;
        out[(b * K + 0) * 3 + 2] = lz;
    }
    __syncthreads();

    // ======================= K-1 sequential iterations ======================
    for (int k = 1; k < K; k++) {
        const int ph = k & 1;

        // phase A: reset other-parity counter; bound-check all chunks
        if (t == 0) swc[ph ^ 1] = 0;
        if (t < NCH) {
            const float* bb = &sbox[t * 6];
            float dx = fmaxf(0.0f, fmaxf(bb[0] - lx, lx - bb[1]));
            float dy = fmaxf(0.0f, fmaxf(bb[2] - ly, ly - bb[3]));
            float dz = fmaxf(0.0f, fmaxf(bb[4] - lz, lz - bb[5]));
            float lb2 = __fmaf_rn(dx, dx, __fmaf_rn(dy, dy, dz * dz));
            float cub = __uint_as_float((u32)(scb[t] >> 32));
            if (lb2 * 0.99999f < cub) {             // conservative margin
                u32 p = atomicAdd(&swc[ph], 1u);
                swl[p] = (u32)t;
            }
        }
        __syncthreads();
        const int nw = (int)swc[ph];

        // phase B: one warp per touched chunk (128 pts, SoA coalesced)
        for (int wi = warp; wi < nw; wi += W) {
            int c = (int)swl[wi];
            int f = c * 32 + lane;
            float4 X = gx4[f];
            float4 Y = gy4[f];
            float4 Z = gz4[f];
            int4   I = gi4[f];
            float4 D = sd4[f];
            const float* Xv = (const float*)&X;
            const float* Yv = (const float*)&Y;
            const float* Zv = (const float*)&Z;
            const int*   Iv = (const int*)&I;
            float* Dv = (float*)&D;
            u64 bk = 0ULL;
            float bx = 0.f, by = 0.f, bz = 0.f;
            #pragma unroll
            for (int cc = 0; cc < 4; cc++) {
                float dx = Xv[cc] - lx, dy = Yv[cc] - ly, dz = Zv[cc] - lz;
                float d2 = __fmaf_rn(dx, dx, __fmaf_rn(dy, dy, dz * dz));
                float nd = fminf(Dv[cc], d2);
                Dv[cc] = nd;
                u64 key = (((u64)__float_as_uint(nd)) << 32) |
                          (u32)(~(u32)Iv[cc]);
                if (key > bk) { bk = key; bx = Xv[cc]; by = Yv[cc]; bz = Zv[cc]; }
            }
            sd4[f] = D;
            #pragma unroll
            for (int o = 16; o > 0; o >>= 1) {
                u64   ok = __shfl_xor_sync(0xffffffffu, bk, o);
                float ox = __shfl_xor_sync(0xffffffffu, bx, o);
                float oy = __shfl_xor_sync(0xffffffffu, by, o);
                float oz = __shfl_xor_sync(0xffffffffu, bz, o);
                if (ok > bk) { bk = ok; bx = ox; by = oy; bz = oz; }
            }
            if (lane == 0) {
                scb[c] = bk;
                scx[c] = bx; scy[c] = by; scz[c] = bz;
            }
        }
        __syncthreads();

        // phase C: warp0 reduces 256 chunk keys, pushes best (key+coords)
        if (warp == 0) {
            u64 bk = 0ULL; int bc = 0;
            #pragma unroll
            for (int i = 0; i < NCH / 32; i++) {
                u64 e = scb[lane + 32 * i];
                if (e > bk) { bk = e; bc = lane + 32 * i; }
            }
            #pragma unroll
            for (int o = 16; o > 0; o >>= 1) {
                u64 ok = __shfl_xor_sync(0xffffffffu, bk, o);
                int oc = __shfl_xor_sync(0xffffffffu, bc, o);
                if (ok > bk) { bk = ok; bc = oc; }
            }
            if (lane == 0) {
                Slot* my = &sl[ph * C + rank];
                uint4 w = make_uint4((u32)(bk & 0xffffffffull),
                                     (u32)(bk >> 32),
                                     __float_as_uint(scx[bc]),
                                     __float_as_uint(scy[bc]));
                float cz = scz[bc];
                #pragma unroll
                for (int r = 0; r < C; r++) {
                    Slot* p = (Slot*)cluster.map_shared_rank(my, r);
                    *(uint4*)p = w;
                    p->z = cz;
                }
            }
        }

        cluster.sync();   // HW-sleep barrier; orders remote slot stores

        // every thread picks the cluster winner from local slots (coords incl.)
        u64 gb = 0ULL;
        float nx = 0.f, ny = 0.f, nz = 0.f;
        #pragma unroll
        for (int r = 0; r < C; r++) {
            const Slot* p = &sl[ph * C + r];
            uint4 w = *(const uint4*)p;
            float z = p->z;
            u64 v = ((u64)w.y << 32) | w.x;
            if (v > gb) {
                gb = v;
                nx = __uint_as_float(w.z);
                ny = __uint_as_float(w.w);
                nz = z;
            }
        }
        lx = nx; ly = ny; lz = nz;

        if (rank == 0 && t == 0) {
            out[(b * K + k) * 3 + 0] = lx;
            out[(b * K + k) * 3 + 1] = ly;
            out[(b * K + k) * 3 + 2] = lz;
        }
    }

    cluster.sync();   // keep SMEM alive until all peer traffic retired
}

extern "C" void kernel_launch(void* const* d_in, const int* in_sizes, int n_in,
                              void* d_out, int out_size) {
    const float* pts  = (const float*)d_in[0];
    const int*   init = (const int*)d_in[1];
    float*       out  = (float*)d_out;

    cudaFuncSetAttribute(fps_kernel,
                         cudaFuncAttributeMaxDynamicSharedMemorySize, SMEM_TOTAL);

    dim3 grid(C, B, 1);
    fps_kernel<<<grid, T, SMEM_TOTAL>>>(pts, init, out);
}